// round 15
// baseline (speedup 1.0000x reference)
#include <cuda_runtime.h>
#include <cuda_fp16.h>
#include <math.h>
#include <stdint.h>

// Problem constants
#define Hh   768
#define Lc   2
#define Vc   32000
#define Bc   128
#define Tc   64
#define Sc   32
#define G4   (4*Hh)   // 3072

// ---------------- scratch (device globals; no allocations allowed) ----------
__device__ __align__(128) float g_G0[(size_t)Tc*Bc*G4]; // layer0 input gates (+biases), gate-major
__device__ __align__(128) float g_c0[Bc*Hh];
__device__ __align__(128) float g_c1[Bc*Hh];
__device__ __align__(128) float g_p1[2][Bc*G4];         // layer1 input-gate partials (permuted cols)
__device__ __align__(128) float g_bp1[G4];              // permuted (b_ih[1]+b_hh[1])
__device__ __align__(128) float g_b0[G4];               // b_ih[0]+b_hh[0] (gate-major)
__device__ unsigned g_bar;                              // grid barrier counter
// xs as fp16 hi/lo (written directly by init gather)
__device__ __align__(128) __half g_xsh[Tc*Bc*Hh];
__device__ __align__(128) __half g_xsl[Tc*Bc*Hh];
// h-state as fp16 hi/lo, ping-pong
__device__ __align__(128) __half g_h0b[2][2][Bc*Hh];
__device__ __align__(128) __half g_h1b[2][2][Bc*Hh];
// recurrence weights: [mat 0=Whh0,1=Wih1,2=Whh1][hi/lo], permuted rows p = h*4+gate
__device__ __align__(128) __half g_Wr[3][2][(size_t)G4*Hh];
// W_ih[0] split (gate-major rows, unpermuted)
__device__ __align__(128) __half g_Wi0[2][(size_t)G4*Hh];
// fp16 split buffers for tensor-core projection (W_out: hi only used by proj)
__device__ __align__(128) __half g_ysh[Tc*Bc*Hh];
__device__ __align__(128) __half g_ysl[Tc*Bc*Hh];
__device__ __align__(128) __half g_Wh[(size_t)Vc*Hh];

// ---------------- mma.sync helpers ------------------------------------------
__device__ __forceinline__ uint32_t smem_u32(const void* p) {
    uint32_t a;
    asm("{ .reg .u64 t; cvta.to.shared.u64 t, %1; cvt.u32.u64 %0, t; }" : "=r"(a) : "l"(p));
    return a;
}
#define LDSM4(r, a) \
    asm volatile("ldmatrix.sync.aligned.m8n8.x4.shared.b16 {%0,%1,%2,%3}, [%4];" \
        : "=r"((r)[0]), "=r"((r)[1]), "=r"((r)[2]), "=r"((r)[3]) : "r"(a))

__device__ __forceinline__ void mma_f16(float* c, const uint32_t* a, const uint32_t* b) {
    asm volatile("mma.sync.aligned.m16n8k16.row.col.f32.f16.f16.f32 "
        "{%0,%1,%2,%3}, {%4,%5,%6,%7}, {%8,%9}, {%0,%1,%2,%3};"
        : "+f"(c[0]), "+f"(c[1]), "+f"(c[2]), "+f"(c[3])
        : "r"(a[0]), "r"(a[1]), "r"(a[2]), "r"(a[3]), "r"(b[0]), "r"(b[1]));
}
__device__ __forceinline__ void cp16(uint32_t dst, const void* src) {       // L2-only (cg)
    asm volatile("cp.async.cg.shared.global [%0], [%1], 16;" :: "r"(dst), "l"(src));
}
__device__ __forceinline__ void cp16ca(uint32_t dst, const void* src) {     // L1-cacheable
    asm volatile("cp.async.ca.shared.global [%0], [%1], 16;" :: "r"(dst), "l"(src));
}
__device__ __forceinline__ void hf_split(float v, __half& h, __half& l) {
    h = __float2half_rz(v);
    l = __float2half_rz(v - __half2float(h));
}

// ---------------- init: gather embeddings (split), init h/c -----------------
__global__ void init_kernel(const int* __restrict__ src, const int* __restrict__ trg,
                            const float* __restrict__ bert, const float* __restrict__ emb) {
    int idx = blockIdx.x * blockDim.x + threadIdx.x;
    if (idx == 0) g_bar = 0;                       // reset grid barrier each run
    if (idx < Tc*Bc*Hh) {
        int h = idx % Hh;
        int m = idx / Hh;          // m = t*Bc + b
        int b = m % Bc;
        int t = m / Bc;
        float v = emb[(size_t)trg[b*Tc + t] * Hh + h];
        __half hh, ll;
        hf_split(v, hh, ll);
        g_xsh[idx] = hh; g_xsl[idx] = ll;
    }
    if (idx < Bc*Hh) {
        int b = idx / Hh;
        float v = bert[(size_t)src[b*Sc] * Hh + (idx % Hh)];
        __half h, l;
        hf_split(v, h, l);
        g_h0b[0][0][idx] = h; g_h0b[0][1][idx] = l;
        g_h1b[0][0][idx] = h; g_h1b[0][1][idx] = l;
        g_c0[idx] = 0.f;
        g_c1[idx] = 0.f;
    }
}

// ---------------- fp16 hi-only split for W_out -------------------------------
__global__ void split_wout(const float* __restrict__ x, __half* __restrict__ hi, int n) {
    int i = blockIdx.x * 256 + threadIdx.x;
    if (i < n) hi[i] = __float2half_rz(x[i]);
}

// ---------------- weight split(+permute) -------------------------------------
__global__ void wsplit(const float* __restrict__ Whh0, const float* __restrict__ Wih1,
                       const float* __restrict__ Whh1, const float* __restrict__ Wih0,
                       const float* __restrict__ bih0, const float* __restrict__ bhh0,
                       const float* __restrict__ bih1, const float* __restrict__ bhh1) {
    int i = blockIdx.x * 256 + threadIdx.x;
    const int per = G4 * Hh;
    if (i < 4*per) {
        int mat = i / per;
        int rem = i % per;
        int r = rem / Hh, k = rem % Hh;
        __half h, l;
        if (mat < 3) {
            const float* srcp = (mat == 0) ? Whh0 : (mat == 1 ? Wih1 : Whh1);
            hf_split(srcp[(size_t)r*Hh + k], h, l);
            int p = (r % Hh)*4 + (r / Hh);
            g_Wr[mat][0][(size_t)p*Hh + k] = h;
            g_Wr[mat][1][(size_t)p*Hh + k] = l;
        } else {
            hf_split(Wih0[(size_t)r*Hh + k], h, l);
            g_Wi0[0][(size_t)r*Hh + k] = h;
            g_Wi0[1][(size_t)r*Hh + k] = l;
        }
    }
    if (i < G4) {
        int p = (i % Hh)*4 + (i / Hh);
        g_bp1[p] = bih1[i] + bhh1[i];
        g_b0[i]  = bih0[i] + bhh0[i];
    }
}

// ---------------- mma hoisted layer0 input GEMM (fp16 3-mma, R10-exact) ------
#define GSTAGE   32768
#define GMMA_SMEM (3*GSTAGE)

__global__ void __launch_bounds__(256) gemm_mma() {
    extern __shared__ char dsm[];
    const uint32_t base = smem_u32(dsm);
    const int tid  = threadIdx.x;
    const int m0   = blockIdx.y * 128;
    const int n0   = blockIdx.x * 128;
    const int lane = tid & 31;
    const int warp = tid >> 5;
    const int wm   = warp >> 2;
    const int wn   = warp & 3;
    const int lr   = lane & 15;
    const int lk   = lane >> 4;
    const int NS   = Hh/32;

    float acc[4][4][4];
    #pragma unroll
    for (int i = 0; i < 4; i++)
        #pragma unroll
        for (int j = 0; j < 4; j++)
            #pragma unroll
            for (int r = 0; r < 4; r++) acc[i][j][r] = 0.f;

    auto load_stage = [&](int buf, int k0) {
        const uint32_t sb = base + buf*GSTAGE;
        #pragma unroll
        for (int i = 0; i < 8; i++) {
            int id  = tid + i*256;
            int arr = id >> 9;
            int w   = id & 511;
            int row = w >> 2, ch = w & 3;
            uint32_t dst = sb + arr*8192 + row*64 + ((ch ^ (row & 3)) << 4);
            const __half* src;
            if      (arr == 0) src = &g_xsh[(size_t)(m0 + row)*Hh + k0 + ch*8];
            else if (arr == 1) src = &g_xsl[(size_t)(m0 + row)*Hh + k0 + ch*8];
            else if (arr == 2) src = &g_Wi0[0][(size_t)(n0 + row)*Hh + k0 + ch*8];
            else               src = &g_Wi0[1][(size_t)(n0 + row)*Hh + k0 + ch*8];
            cp16(dst, src);
        }
        asm volatile("cp.async.commit_group;" ::: "memory");
    };

    load_stage(0, 0);
    load_stage(1, 32);

    for (int s = 0; s < NS; ++s) {
        if (s + 1 < NS) { asm volatile("cp.async.wait_group 1;" ::: "memory"); }
        else            { asm volatile("cp.async.wait_group 0;" ::: "memory"); }
        __syncthreads();
        if (s + 2 < NS) load_stage((s+2)%3, (s+2)*32);

        const uint32_t sb = base + (s%3)*GSTAGE;
        #pragma unroll
        for (int kk8 = 0; kk8 < 4; kk8 += 2) {
            uint32_t ah[4][4], al[4][4];
            #pragma unroll
            for (int mt = 0; mt < 4; mt++) {
                int row = wm*64 + mt*16 + lr;
                uint32_t off = row*64 + ((((kk8 + lk) ^ (row & 3))) << 4);
                LDSM4(ah[mt], sb + off);
                LDSM4(al[mt], sb + 8192 + off);
            }
            uint32_t bh[4][2], bl[4][2];
            #pragma unroll
            for (int np = 0; np < 2; np++) {
                int row = wn*32 + np*16 + lr;
                uint32_t off = row*64 + ((((kk8 + lk) ^ (row & 3))) << 4);
                uint32_t r[4];
                LDSM4(r, sb + 16384 + off);
                bh[np*2][0]=r[0]; bh[np*2+1][0]=r[1]; bh[np*2][1]=r[2]; bh[np*2+1][1]=r[3];
                LDSM4(r, sb + 24576 + off);
                bl[np*2][0]=r[0]; bl[np*2+1][0]=r[1]; bl[np*2][1]=r[2]; bl[np*2+1][1]=r[3];
            }
            #pragma unroll
            for (int mt = 0; mt < 4; mt++)
                #pragma unroll
                for (int nt = 0; nt < 4; nt++) {
                    mma_f16(acc[mt][nt], ah[mt], bh[nt]);
                    mma_f16(acc[mt][nt], ah[mt], bl[nt]);
                    mma_f16(acc[mt][nt], al[mt], bh[nt]);
                }
        }
    }

    #pragma unroll
    for (int nt = 0; nt < 4; nt++) {
        int col = n0 + wn*32 + nt*8 + (lane & 3)*2;
        float bb0 = g_b0[col], bb1 = g_b0[col + 1];
        #pragma unroll
        for (int mt = 0; mt < 4; mt++) {
            int r0 = m0 + wm*64 + mt*16 + (lane >> 2);
            *reinterpret_cast<float2*>(&g_G0[(size_t)r0*G4 + col]) =
                make_float2(acc[mt][nt][0] + bb0, acc[mt][nt][1] + bb1);
            *reinterpret_cast<float2*>(&g_G0[(size_t)(r0+8)*G4 + col]) =
                make_float2(acc[mt][nt][2] + bb0, acc[mt][nt][3] + bb1);
        }
    }
}

// ---------------- persistent mma recurrence (R13-exact, 288 CTAs) ------------
#define SSTAGE 32768   // Ah 8K | Al 8K | Bh 8K | Bl 8K
#define STEP_SMEM (3*SSTAGE)
#define NSLOTS 66
#define GRID_STEP 288
#define SNK (Hh/64)    // 12 k-chunks

__global__ void __launch_bounds__(256, 2) step_persist() {
    extern __shared__ char dsm[];
    const uint32_t base = smem_u32(dsm);
    const int tid  = threadIdx.x;
    const int bx   = blockIdx.x;
    const int lane = tid & 31;
    const int warp = tid >> 5;
    const int wm   = warp >> 2;        // 0..1 (m 32 each)
    const int wn   = warp & 3;         // 0..3 (n 16 each)
    const int lr   = lane & 15;
    const int lk   = lane >> 4;

    int role, nb, mh;
    const __half *Bh, *Bl;
    if (bx < 96)       { role = 0; nb = bx >> 1;         Bh = g_Wr[0][0]; Bl = g_Wr[0][1]; }
    else if (bx < 192) { role = 1; nb = (bx - 96) >> 1;  Bh = g_Wr[1][0]; Bl = g_Wr[1][1]; }
    else               { role = 2; nb = (bx - 192) >> 1; Bh = g_Wr[2][0]; Bl = g_Wr[2][1]; }
    mh = bx & 1;
    const int n0  = nb * 64;
    const int am0 = mh * 64;           // batch-half row offset
    float* gsh = reinterpret_cast<float*>(dsm + SSTAGE);   // [64][68]

    auto prefetch_B0 = [&]() {
        #pragma unroll
        for (int q = 0; q < 2; ++q) {
            int id  = tid + q*256;
            int row = id >> 3, ch = id & 7;
            uint32_t off = row*128 + ((ch ^ (row & 7)) << 4);
            cp16ca(base + 16384 + off, &Bh[(size_t)(n0 + row)*Hh + ch*8]);
            cp16ca(base + 24576 + off, &Bl[(size_t)(n0 + row)*Hh + ch*8]);
        }
    };

    if (role == 0) prefetch_B0();

    for (int s = 0; s < NSLOTS; ++s) {
        bool active = (role == 0) ? (s < 64) : (role == 1) ? (s >= 1 && s <= 64) : (s >= 2);
        if (active) {
            const __half* Ah = (role == 2) ? g_h1b[s & 1][0] : g_h0b[s & 1][0];
            const __half* Al = (role == 2) ? g_h1b[s & 1][1] : g_h0b[s & 1][1];

            float acc[2][2][4];
            #pragma unroll
            for (int i = 0; i < 2; i++)
                #pragma unroll
                for (int j = 0; j < 2; j++)
                    #pragma unroll
                    for (int r = 0; r < 4; r++) acc[i][j][r] = 0.f;

            auto load_full = [&](int buf, int k0) {
                const uint32_t sb = base + buf*SSTAGE;
                #pragma unroll
                for (int q = 0; q < 2; ++q) {
                    int id  = tid + q*256;
                    int row = id >> 3, ch = id & 7;
                    uint32_t off = row*128 + ((ch ^ (row & 7)) << 4);
                    cp16(sb + off,           &Ah[(size_t)(am0 + row)*Hh + k0 + ch*8]);
                    cp16(sb + 8192  + off,   &Al[(size_t)(am0 + row)*Hh + k0 + ch*8]);
                    cp16ca(sb + 16384 + off, &Bh[(size_t)(n0 + row)*Hh + k0 + ch*8]);
                    cp16ca(sb + 24576 + off, &Bl[(size_t)(n0 + row)*Hh + k0 + ch*8]);
                }
                asm volatile("cp.async.commit_group;" ::: "memory");
            };

            {
                #pragma unroll
                for (int q = 0; q < 2; ++q) {
                    int id  = tid + q*256;
                    int row = id >> 3, ch = id & 7;
                    uint32_t off = row*128 + ((ch ^ (row & 7)) << 4);
                    cp16(base + off,          &Ah[(size_t)(am0 + row)*Hh + ch*8]);
                    cp16(base + 8192  + off,  &Al[(size_t)(am0 + row)*Hh + ch*8]);
                }
                asm volatile("cp.async.commit_group;" ::: "memory");
            }
            load_full(1, 64);

            for (int st = 0; st < SNK; ++st) {
                if (st == SNK-1) { asm volatile("cp.async.wait_group 0;" ::: "memory"); }
                else             { asm volatile("cp.async.wait_group 1;" ::: "memory"); }
                __syncthreads();
                if (st + 2 < SNK) load_full((st+2)%3, (st+2)*64);

                const uint32_t sb = base + (st%3)*SSTAGE;
                #pragma unroll
                for (int kk8 = 0; kk8 < 8; kk8 += 2) {
                    uint32_t ah[2][4], al[2][4];
                    #pragma unroll
                    for (int mt = 0; mt < 2; mt++) {
                        int row = wm*32 + mt*16 + lr;
                        uint32_t off = row*128 + ((((kk8 + lk) ^ (row & 7))) << 4);
                        LDSM4(ah[mt], sb + off);
                        LDSM4(al[mt], sb + 8192 + off);
                    }
                    uint32_t bh[2][2], bl[2][2];
                    {
                        int row = wn*16 + lr;
                        uint32_t off = row*128 + ((((kk8 + lk) ^ (row & 7))) << 4);
                        uint32_t r[4];
                        LDSM4(r, sb + 16384 + off);
                        bh[0][0]=r[0]; bh[1][0]=r[1]; bh[0][1]=r[2]; bh[1][1]=r[3];
                        LDSM4(r, sb + 24576 + off);
                        bl[0][0]=r[0]; bl[1][0]=r[1]; bl[0][1]=r[2]; bl[1][1]=r[3];
                    }
                    #pragma unroll
                    for (int mt = 0; mt < 2; mt++)
                        #pragma unroll
                        for (int nt = 0; nt < 2; nt++) {
                            mma_f16(acc[mt][nt], ah[mt], bh[nt]);
                            mma_f16(acc[mt][nt], ah[mt], bl[nt]);
                            mma_f16(acc[mt][nt], al[mt], bh[nt]);
                        }
                }
            }
            __syncthreads();

            if (role == 1) {
                float* pbuf = g_p1[(s-1) & 1];
                #pragma unroll
                for (int mt = 0; mt < 2; mt++)
                    #pragma unroll
                    for (int nt = 0; nt < 2; nt++) {
                        int r0  = am0 + wm*32 + mt*16 + (lane >> 2);
                        int col = n0 + wn*16 + nt*8 + (lane & 3)*2;
                        *reinterpret_cast<float2*>(&pbuf[(size_t)r0*G4 + col]) =
                            make_float2(acc[mt][nt][0], acc[mt][nt][1]);
                        *reinterpret_cast<float2*>(&pbuf[(size_t)(r0+8)*G4 + col]) =
                            make_float2(acc[mt][nt][2], acc[mt][nt][3]);
                    }
            } else {
                #pragma unroll
                for (int mt = 0; mt < 2; mt++)
                    #pragma unroll
                    for (int nt = 0; nt < 2; nt++) {
                        int r0 = wm*32 + mt*16 + (lane >> 2);
                        int c  = wn*16 + nt*8 + (lane & 3)*2;
                        *reinterpret_cast<float2*>(&gsh[r0*68 + c]) =
                            make_float2(acc[mt][nt][0], acc[mt][nt][1]);
                        *reinterpret_cast<float2*>(&gsh[(r0+8)*68 + c]) =
                            make_float2(acc[mt][nt][2], acc[mt][nt][3]);
                    }
                __syncthreads();

                const int hg = nb * 16;
                if (role == 0) {
                    __half* Ho = g_h0b[(s & 1) ^ 1][0];
                    __half* Lo = g_h0b[(s & 1) ^ 1][1];
                    for (int e = tid; e < 64*16; e += 256) {
                        int br = e >> 4, hl = e & 15;
                        int b = am0 + br;
                        float4 g = *reinterpret_cast<const float4*>(&gsh[br*68 + hl*4]);
                        int h = hg + hl;
                        size_t gb = ((size_t)(s*Bc + b))*G4 + h;
                        float gi = g.x + g_G0[gb];
                        float gf = g.y + g_G0[gb +   Hh];
                        float gg = g.z + g_G0[gb + 2*Hh];
                        float go = g.w + g_G0[gb + 3*Hh];
                        int ci = b*Hh + h;
                        float si = 1.f/(1.f+expf(-gi));
                        float sf = 1.f/(1.f+expf(-gf));
                        float so = 1.f/(1.f+expf(-go));
                        float cn = sf * g_c0[ci] + si * tanhf(gg);
                        float hn = so * tanhf(cn);
                        g_c0[ci] = cn;
                        __half hh, ll;
                        hf_split(hn, hh, ll);
                        Ho[ci] = hh; Lo[ci] = ll;
                    }
                } else {
                    const int u = s - 2;
                    const float* pbuf = g_p1[u & 1];
                    __half* Ho = g_h1b[(s & 1) ^ 1][0];
                    __half* Lo = g_h1b[(s & 1) ^ 1][1];
                    for (int e = tid; e < 64*16; e += 256) {
                        int br = e >> 4, hl = e & 15;
                        int b = am0 + br;
                        float4 g = *reinterpret_cast<const float4*>(&gsh[br*68 + hl*4]);
                        int h = hg + hl;
                        float4 p  = __ldcg(reinterpret_cast<const float4*>(&pbuf[(size_t)b*G4 + h*4]));
                        float4 bb = *reinterpret_cast<const float4*>(&g_bp1[h*4]);
                        float gi = g.x + p.x + bb.x;
                        float gf = g.y + p.y + bb.y;
                        float gg = g.z + p.z + bb.z;
                        float go = g.w + p.w + bb.w;
                        int ci = b*Hh + h;
                        float si = 1.f/(1.f+expf(-gi));
                        float sf = 1.f/(1.f+expf(-gf));
                        float so = 1.f/(1.f+expf(-go));
                        float cn = sf * g_c1[ci] + si * tanhf(gg);
                        float hn = so * tanhf(cn);
                        g_c1[ci] = cn;
                        __half hh, ll;
                        hf_split(hn, hh, ll);
                        Ho[ci] = hh; Lo[ci] = ll;
                        size_t yo = ((size_t)u*Bc + b)*Hh + h;
                        g_ysh[yo] = hh; g_ysl[yo] = ll;
                    }
                }
            }
        }

        if (s + 1 < NSLOTS) {
            bool active_next = (role == 0) ? (s+1 < 64)
                             : (role == 1) ? (s+1 >= 1 && s+1 <= 64)
                             : (s+1 >= 2);
            if (active) __syncthreads();
            if (active_next) prefetch_B0();
            __syncthreads();
            if (tid == 0) {
                unsigned* bar = &g_bar;
                asm volatile("red.release.gpu.global.add.u32 [%0], 1;" :: "l"(bar) : "memory");
                unsigned target = (unsigned)GRID_STEP * (unsigned)(s + 1);
                unsigned v;
                do {
                    asm volatile("ld.acquire.gpu.global.u32 %0, [%1];" : "=r"(v) : "l"(bar) : "memory");
                    if (v >= target) break;
                    asm volatile("nanosleep.u32 64;");
                } while (true);
            }
            __syncthreads();
        }
    }
}

// ---------------- fp16 2-mma output projection (128x256 tile, 512 threads) ---
// Halves A(ys) L2 traffic vs 128x128 tiles: 9.4 GB -> 6.3 GB total.
#define PSTAGE   65536     // Ah 16K | Al 16K | Bh 32K   (k-chunk 64)
#define PROJ_SMEM (2*PSTAGE)
#define PNK (Hh/64)        // 12 k-chunks

__global__ void __launch_bounds__(512, 1) proj_mma(const float* __restrict__ b_out,
                                                   float* __restrict__ out) {
    extern __shared__ char dsm[];
    const uint32_t base = smem_u32(dsm);
    const int tid  = threadIdx.x;
    const int t    = blockIdx.x;
    const int m0   = t * 128;
    const int n0   = blockIdx.y * 256;
    const int lane = tid & 31;
    const int warp = tid >> 5;        // 0..15
    const int wm   = warp >> 2;       // 0..3 (m 32 each)
    const int wn   = warp & 3;        // 0..3 (n 64 each)
    const int lr   = lane & 15;
    const int lk   = lane >> 4;

    float acc[2][8][4];
    #pragma unroll
    for (int i = 0; i < 2; i++)
        #pragma unroll
        for (int j = 0; j < 8; j++)
            #pragma unroll
            for (int r = 0; r < 4; r++) acc[i][j][r] = 0.f;

    auto load_stage = [&](int buf, int k0) {
        const uint32_t sb = base + buf*PSTAGE;
        #pragma unroll
        for (int i = 0; i < 8; i++) {
            int id = tid + i*512;          // 0..4095
            if (id < 2048) {               // A: hi (0..1023), lo (1024..2047)
                int arr = id >> 10;
                int w   = id & 1023;
                int row = w >> 3, ch = w & 7;
                uint32_t dst = sb + arr*16384 + row*128 + ((ch ^ (row & 7)) << 4);
                const __half* src = (arr == 0)
                    ? &g_ysh[(size_t)(m0 + row)*Hh + k0 + ch*8]
                    : &g_ysl[(size_t)(m0 + row)*Hh + k0 + ch*8];
                cp16(dst, src);
            } else {                       // B hi: 256 rows
                int w   = id - 2048;       // 0..2047
                int row = w >> 3, ch = w & 7;
                uint32_t dst = sb + 32768 + row*128 + ((ch ^ (row & 7)) << 4);
                cp16(dst, &g_Wh[(size_t)(n0 + row)*Hh + k0 + ch*8]);
            }
        }
        asm volatile("cp.async.commit_group;" ::: "memory");
    };

    load_stage(0, 0);

    for (int s = 0; s < PNK; ++s) {
        asm volatile("cp.async.wait_group 0;" ::: "memory");
        __syncthreads();
        if (s + 1 < PNK) load_stage((s+1) & 1, (s+1)*64);

        const uint32_t sb = base + (s & 1)*PSTAGE;
        #pragma unroll
        for (int kk8 = 0; kk8 < 8; kk8 += 2) {
            uint32_t ah[2][4], al[2][4];
            #pragma unroll
            for (int mt = 0; mt < 2; mt++) {
                int row = wm*32 + mt*16 + lr;
                uint32_t off = row*128 + ((((kk8 + lk) ^ (row & 7))) << 4);
                LDSM4(ah[mt], sb + off);
                LDSM4(al[mt], sb + 16384 + off);
            }
            uint32_t bh[8][2];
            #pragma unroll
            for (int np = 0; np < 4; np++) {
                int row = wn*64 + np*16 + lr;
                uint32_t off = row*128 + ((((kk8 + lk) ^ (row & 7))) << 4);
                uint32_t r[4];
                LDSM4(r, sb + 32768 + off);
                bh[np*2][0]=r[0]; bh[np*2+1][0]=r[1]; bh[np*2][1]=r[2]; bh[np*2+1][1]=r[3];
            }
            #pragma unroll
            for (int mt = 0; mt < 2; mt++)
                #pragma unroll
                for (int nt = 0; nt < 8; nt++) {
                    mma_f16(acc[mt][nt], ah[mt], bh[nt]);
                    mma_f16(acc[mt][nt], al[mt], bh[nt]);
                }
        }
    }

    #pragma unroll
    for (int nt = 0; nt < 8; nt++) {
        int col = n0 + wn*64 + nt*8 + (lane & 3)*2;
        float bb0 = b_out[col], bb1 = b_out[col + 1];
        #pragma unroll
        for (int mt = 0; mt < 2; mt++) {
            int r0 = wm*32 + mt*16 + (lane >> 2);
            float2* p0 = reinterpret_cast<float2*>(&out[((size_t)r0*Tc + t)*Vc + col]);
            *p0 = make_float2(acc[mt][nt][0] + bb0, acc[mt][nt][1] + bb1);
            float2* p1 = reinterpret_cast<float2*>(&out[((size_t)(r0+8)*Tc + t)*Vc + col]);
            *p1 = make_float2(acc[mt][nt][2] + bb0, acc[mt][nt][3] + bb1);
        }
    }
}

// ---------------- launch ----------------------------------------------------
extern "C" void kernel_launch(void* const* d_in, const int* in_sizes, int n_in,
                              void* d_out, int out_size) {
    const int*   src   = (const int*)  d_in[0];
    const int*   trg   = (const int*)  d_in[1];
    const float* bert  = (const float*)d_in[2];
    const float* emb   = (const float*)d_in[3];
    const float* W_ih  = (const float*)d_in[4];
    const float* W_hh  = (const float*)d_in[5];
    const float* b_ih  = (const float*)d_in[6];
    const float* b_hh  = (const float*)d_in[7];
    const float* W_out = (const float*)d_in[8];
    const float* b_out = (const float*)d_in[9];
    float* out = (float*)d_out;

    cudaFuncSetAttribute(proj_mma,     cudaFuncAttributeMaxDynamicSharedMemorySize, PROJ_SMEM);
    cudaFuncSetAttribute(step_persist, cudaFuncAttributeMaxDynamicSharedMemorySize, STEP_SMEM);
    cudaFuncSetAttribute(gemm_mma,     cudaFuncAttributeMaxDynamicSharedMemorySize, GMMA_SMEM);

    // 1. gather embeddings (fp16-split xs) + init h/c + reset grid barrier
    init_kernel<<<(Tc*Bc*Hh + 255)/256, 256>>>(src, trg, bert, emb);

    // 1b. W_out hi-only fp16
    __half* wh;
    cudaGetSymbolAddress((void**)&wh, g_Wh);
    split_wout<<<(Vc*Hh + 255)/256, 256>>>(W_out, wh, Vc*Hh);

    // 1c. split (+permute) all LSTM weights + biases (fp16 hi/lo)
    const float* Wih0 = W_ih;
    const float* Whh0 = W_hh;
    const float* Wih1 = W_ih + (size_t)G4 * Hh;
    const float* Whh1 = W_hh + (size_t)G4 * Hh;
    wsplit<<<(4*G4*Hh + 255)/256, 256>>>(Whh0, Wih1, Whh1, Wih0,
                                         b_ih, b_hh, b_ih + G4, b_hh + G4);

    // 2. hoisted layer-0 input GEMM on tensor cores (fp16 3-mma)
    gemm_mma<<<dim3(G4/128, (Tc*Bc)/128), 256, GMMA_SMEM>>>();

    // 3. persistent recurrence: 288 CTAs (2/SM), grid barrier per slot
    step_persist<<<GRID_STEP, 256, STEP_SMEM>>>();

    // 4. output projection on tensor cores (fp16 2-mma, 128x256 tile)
    proj_mma<<<dim3(Tc, Vc/256), 512, PROJ_SMEM>>>(b_out, out);
}

// round 16
// speedup vs baseline: 1.3481x; 1.3481x over previous
#include <cuda_runtime.h>
#include <cuda_fp16.h>
#include <math.h>
#include <stdint.h>

// Problem constants
#define Hh   768
#define Lc   2
#define Vc   32000
#define Bc   128
#define Tc   64
#define Sc   32
#define G4   (4*Hh)   // 3072

// ---------------- scratch (device globals; no allocations allowed) ----------
__device__ __align__(128) float g_G0[(size_t)Tc*Bc*G4]; // layer0 input gates (+biases), gate-major
__device__ __align__(128) float g_c0[Bc*Hh];
__device__ __align__(128) float g_c1[Bc*Hh];
__device__ __align__(128) float g_p1[2][Bc*G4];         // layer1 input-gate partials (permuted cols)
__device__ __align__(128) float g_bp1[G4];              // permuted (b_ih[1]+b_hh[1])
__device__ __align__(128) float g_b0[G4];               // b_ih[0]+b_hh[0] (gate-major)
__device__ unsigned g_bar;                              // grid barrier counter
// xs as fp16 hi/lo (written directly by init gather)
__device__ __align__(128) __half g_xsh[Tc*Bc*Hh];
__device__ __align__(128) __half g_xsl[Tc*Bc*Hh];
// h-state as fp16 hi/lo, ping-pong
__device__ __align__(128) __half g_h0b[2][2][Bc*Hh];
__device__ __align__(128) __half g_h1b[2][2][Bc*Hh];
// recurrence weights: [mat 0=Whh0,1=Wih1,2=Whh1][hi/lo], permuted rows p = h*4+gate
__device__ __align__(128) __half g_Wr[3][2][(size_t)G4*Hh];
// W_ih[0] split (gate-major rows, unpermuted)
__device__ __align__(128) __half g_Wi0[2][(size_t)G4*Hh];
// fp16 buffers for tensor-core projection (hi only; proj is 1-mma AhBh)
__device__ __align__(128) __half g_ysh[Tc*Bc*Hh];
__device__ __align__(128) __half g_Wh[(size_t)Vc*Hh];

// ---------------- mma.sync helpers ------------------------------------------
__device__ __forceinline__ uint32_t smem_u32(const void* p) {
    uint32_t a;
    asm("{ .reg .u64 t; cvta.to.shared.u64 t, %1; cvt.u32.u64 %0, t; }" : "=r"(a) : "l"(p));
    return a;
}
#define LDSM4(r, a) \
    asm volatile("ldmatrix.sync.aligned.m8n8.x4.shared.b16 {%0,%1,%2,%3}, [%4];" \
        : "=r"((r)[0]), "=r"((r)[1]), "=r"((r)[2]), "=r"((r)[3]) : "r"(a))

__device__ __forceinline__ void mma_f16(float* c, const uint32_t* a, const uint32_t* b) {
    asm volatile("mma.sync.aligned.m16n8k16.row.col.f32.f16.f16.f32 "
        "{%0,%1,%2,%3}, {%4,%5,%6,%7}, {%8,%9}, {%0,%1,%2,%3};"
        : "+f"(c[0]), "+f"(c[1]), "+f"(c[2]), "+f"(c[3])
        : "r"(a[0]), "r"(a[1]), "r"(a[2]), "r"(a[3]), "r"(b[0]), "r"(b[1]));
}
__device__ __forceinline__ void cp16(uint32_t dst, const void* src) {       // L2-only (cg)
    asm volatile("cp.async.cg.shared.global [%0], [%1], 16;" :: "r"(dst), "l"(src));
}
__device__ __forceinline__ void cp16ca(uint32_t dst, const void* src) {     // L1-cacheable
    asm volatile("cp.async.ca.shared.global [%0], [%1], 16;" :: "r"(dst), "l"(src));
}
__device__ __forceinline__ void hf_split(float v, __half& h, __half& l) {
    h = __float2half_rz(v);
    l = __float2half_rz(v - __half2float(h));
}

// ---------------- init: gather embeddings (split), init h/c -----------------
__global__ void init_kernel(const int* __restrict__ src, const int* __restrict__ trg,
                            const float* __restrict__ bert, const float* __restrict__ emb) {
    int idx = blockIdx.x * blockDim.x + threadIdx.x;
    if (idx == 0) g_bar = 0;                       // reset grid barrier each run
    if (idx < Tc*Bc*Hh) {
        int h = idx % Hh;
        int m = idx / Hh;          // m = t*Bc + b
        int b = m % Bc;
        int t = m / Bc;
        float v = emb[(size_t)trg[b*Tc + t] * Hh + h];
        __half hh, ll;
        hf_split(v, hh, ll);
        g_xsh[idx] = hh; g_xsl[idx] = ll;
    }
    if (idx < Bc*Hh) {
        int b = idx / Hh;
        float v = bert[(size_t)src[b*Sc] * Hh + (idx % Hh)];
        __half h, l;
        hf_split(v, h, l);
        g_h0b[0][0][idx] = h; g_h0b[0][1][idx] = l;
        g_h1b[0][0][idx] = h; g_h1b[0][1][idx] = l;
        g_c0[idx] = 0.f;
        g_c1[idx] = 0.f;
    }
}

// ---------------- fp16 hi-only split for W_out -------------------------------
__global__ void split_wout(const float* __restrict__ x, __half* __restrict__ hi, int n) {
    int i = blockIdx.x * 256 + threadIdx.x;
    if (i < n) hi[i] = __float2half_rz(x[i]);
}

// ---------------- weight split(+permute) -------------------------------------
__global__ void wsplit(const float* __restrict__ Whh0, const float* __restrict__ Wih1,
                       const float* __restrict__ Whh1, const float* __restrict__ Wih0,
                       const float* __restrict__ bih0, const float* __restrict__ bhh0,
                       const float* __restrict__ bih1, const float* __restrict__ bhh1) {
    int i = blockIdx.x * 256 + threadIdx.x;
    const int per = G4 * Hh;
    if (i < 4*per) {
        int mat = i / per;
        int rem = i % per;
        int r = rem / Hh, k = rem % Hh;
        __half h, l;
        if (mat < 3) {
            const float* srcp = (mat == 0) ? Whh0 : (mat == 1 ? Wih1 : Whh1);
            hf_split(srcp[(size_t)r*Hh + k], h, l);
            int p = (r % Hh)*4 + (r / Hh);
            g_Wr[mat][0][(size_t)p*Hh + k] = h;
            g_Wr[mat][1][(size_t)p*Hh + k] = l;
        } else {
            hf_split(Wih0[(size_t)r*Hh + k], h, l);
            g_Wi0[0][(size_t)r*Hh + k] = h;
            g_Wi0[1][(size_t)r*Hh + k] = l;
        }
    }
    if (i < G4) {
        int p = (i % Hh)*4 + (i / Hh);
        g_bp1[p] = bih1[i] + bhh1[i];
        g_b0[i]  = bih0[i] + bhh0[i];
    }
}

// ---------------- mma hoisted layer0 input GEMM (fp16 3-mma, R10-exact) ------
#define GSTAGE   32768
#define GMMA_SMEM (3*GSTAGE)

__global__ void __launch_bounds__(256) gemm_mma() {
    extern __shared__ char dsm[];
    const uint32_t base = smem_u32(dsm);
    const int tid  = threadIdx.x;
    const int m0   = blockIdx.y * 128;
    const int n0   = blockIdx.x * 128;
    const int lane = tid & 31;
    const int warp = tid >> 5;
    const int wm   = warp >> 2;
    const int wn   = warp & 3;
    const int lr   = lane & 15;
    const int lk   = lane >> 4;
    const int NS   = Hh/32;

    float acc[4][4][4];
    #pragma unroll
    for (int i = 0; i < 4; i++)
        #pragma unroll
        for (int j = 0; j < 4; j++)
            #pragma unroll
            for (int r = 0; r < 4; r++) acc[i][j][r] = 0.f;

    auto load_stage = [&](int buf, int k0) {
        const uint32_t sb = base + buf*GSTAGE;
        #pragma unroll
        for (int i = 0; i < 8; i++) {
            int id  = tid + i*256;
            int arr = id >> 9;
            int w   = id & 511;
            int row = w >> 2, ch = w & 3;
            uint32_t dst = sb + arr*8192 + row*64 + ((ch ^ (row & 3)) << 4);
            const __half* src;
            if      (arr == 0) src = &g_xsh[(size_t)(m0 + row)*Hh + k0 + ch*8];
            else if (arr == 1) src = &g_xsl[(size_t)(m0 + row)*Hh + k0 + ch*8];
            else if (arr == 2) src = &g_Wi0[0][(size_t)(n0 + row)*Hh + k0 + ch*8];
            else               src = &g_Wi0[1][(size_t)(n0 + row)*Hh + k0 + ch*8];
            cp16(dst, src);
        }
        asm volatile("cp.async.commit_group;" ::: "memory");
    };

    load_stage(0, 0);
    load_stage(1, 32);

    for (int s = 0; s < NS; ++s) {
        if (s + 1 < NS) { asm volatile("cp.async.wait_group 1;" ::: "memory"); }
        else            { asm volatile("cp.async.wait_group 0;" ::: "memory"); }
        __syncthreads();
        if (s + 2 < NS) load_stage((s+2)%3, (s+2)*32);

        const uint32_t sb = base + (s%3)*GSTAGE;
        #pragma unroll
        for (int kk8 = 0; kk8 < 4; kk8 += 2) {
            uint32_t ah[4][4], al[4][4];
            #pragma unroll
            for (int mt = 0; mt < 4; mt++) {
                int row = wm*64 + mt*16 + lr;
                uint32_t off = row*64 + ((((kk8 + lk) ^ (row & 3))) << 4);
                LDSM4(ah[mt], sb + off);
                LDSM4(al[mt], sb + 8192 + off);
            }
            uint32_t bh[4][2], bl[4][2];
            #pragma unroll
            for (int np = 0; np < 2; np++) {
                int row = wn*32 + np*16 + lr;
                uint32_t off = row*64 + ((((kk8 + lk) ^ (row & 3))) << 4);
                uint32_t r[4];
                LDSM4(r, sb + 16384 + off);
                bh[np*2][0]=r[0]; bh[np*2+1][0]=r[1]; bh[np*2][1]=r[2]; bh[np*2+1][1]=r[3];
                LDSM4(r, sb + 24576 + off);
                bl[np*2][0]=r[0]; bl[np*2+1][0]=r[1]; bl[np*2][1]=r[2]; bl[np*2+1][1]=r[3];
            }
            #pragma unroll
            for (int mt = 0; mt < 4; mt++)
                #pragma unroll
                for (int nt = 0; nt < 4; nt++) {
                    mma_f16(acc[mt][nt], ah[mt], bh[nt]);
                    mma_f16(acc[mt][nt], ah[mt], bl[nt]);
                    mma_f16(acc[mt][nt], al[mt], bh[nt]);
                }
        }
    }

    #pragma unroll
    for (int nt = 0; nt < 4; nt++) {
        int col = n0 + wn*32 + nt*8 + (lane & 3)*2;
        float bb0 = g_b0[col], bb1 = g_b0[col + 1];
        #pragma unroll
        for (int mt = 0; mt < 4; mt++) {
            int r0 = m0 + wm*64 + mt*16 + (lane >> 2);
            *reinterpret_cast<float2*>(&g_G0[(size_t)r0*G4 + col]) =
                make_float2(acc[mt][nt][0] + bb0, acc[mt][nt][1] + bb1);
            *reinterpret_cast<float2*>(&g_G0[(size_t)(r0+8)*G4 + col]) =
                make_float2(acc[mt][nt][2] + bb0, acc[mt][nt][3] + bb1);
        }
    }
}

// ---------------- persistent mma recurrence (R10-exact, 288 CTAs) ------------
#define SSTAGE 32768   // Ah 8K | Al 8K | Bh 8K | Bl 8K
#define STEP_SMEM (3*SSTAGE)
#define NSLOTS 66
#define GRID_STEP 288
#define SNK (Hh/64)    // 12 k-chunks

__global__ void __launch_bounds__(256, 2) step_persist() {
    extern __shared__ char dsm[];
    const uint32_t base = smem_u32(dsm);
    const int tid  = threadIdx.x;
    const int bx   = blockIdx.x;
    const int lane = tid & 31;
    const int warp = tid >> 5;
    const int wm   = warp >> 2;        // 0..1 (m 32 each)
    const int wn   = warp & 3;         // 0..3 (n 16 each)
    const int lr   = lane & 15;
    const int lk   = lane >> 4;

    int role, nb, mh;
    const __half *Bh, *Bl;
    if (bx < 96)       { role = 0; nb = bx >> 1;         Bh = g_Wr[0][0]; Bl = g_Wr[0][1]; }
    else if (bx < 192) { role = 1; nb = (bx - 96) >> 1;  Bh = g_Wr[1][0]; Bl = g_Wr[1][1]; }
    else               { role = 2; nb = (bx - 192) >> 1; Bh = g_Wr[2][0]; Bl = g_Wr[2][1]; }
    mh = bx & 1;
    const int n0  = nb * 64;
    const int am0 = mh * 64;           // batch-half row offset
    float* gsh = reinterpret_cast<float*>(dsm + SSTAGE);   // [64][68]

    auto prefetch_B0 = [&]() {
        #pragma unroll
        for (int q = 0; q < 2; ++q) {
            int id  = tid + q*256;
            int row = id >> 3, ch = id & 7;
            uint32_t off = row*128 + ((ch ^ (row & 7)) << 4);
            cp16ca(base + 16384 + off, &Bh[(size_t)(n0 + row)*Hh + ch*8]);
            cp16ca(base + 24576 + off, &Bl[(size_t)(n0 + row)*Hh + ch*8]);
        }
    };

    if (role == 0) prefetch_B0();

    for (int s = 0; s < NSLOTS; ++s) {
        bool active = (role == 0) ? (s < 64) : (role == 1) ? (s >= 1 && s <= 64) : (s >= 2);
        if (active) {
            const __half* Ah = (role == 2) ? g_h1b[s & 1][0] : g_h0b[s & 1][0];
            const __half* Al = (role == 2) ? g_h1b[s & 1][1] : g_h0b[s & 1][1];

            float acc[2][2][4];
            #pragma unroll
            for (int i = 0; i < 2; i++)
                #pragma unroll
                for (int j = 0; j < 2; j++)
                    #pragma unroll
                    for (int r = 0; r < 4; r++) acc[i][j][r] = 0.f;

            auto load_full = [&](int buf, int k0) {
                const uint32_t sb = base + buf*SSTAGE;
                #pragma unroll
                for (int q = 0; q < 2; ++q) {
                    int id  = tid + q*256;
                    int row = id >> 3, ch = id & 7;
                    uint32_t off = row*128 + ((ch ^ (row & 7)) << 4);
                    cp16(sb + off,           &Ah[(size_t)(am0 + row)*Hh + k0 + ch*8]);
                    cp16(sb + 8192  + off,   &Al[(size_t)(am0 + row)*Hh + k0 + ch*8]);
                    cp16ca(sb + 16384 + off, &Bh[(size_t)(n0 + row)*Hh + k0 + ch*8]);
                    cp16ca(sb + 24576 + off, &Bl[(size_t)(n0 + row)*Hh + k0 + ch*8]);
                }
                asm volatile("cp.async.commit_group;" ::: "memory");
            };

            {
                #pragma unroll
                for (int q = 0; q < 2; ++q) {
                    int id  = tid + q*256;
                    int row = id >> 3, ch = id & 7;
                    uint32_t off = row*128 + ((ch ^ (row & 7)) << 4);
                    cp16(base + off,          &Ah[(size_t)(am0 + row)*Hh + ch*8]);
                    cp16(base + 8192  + off,  &Al[(size_t)(am0 + row)*Hh + ch*8]);
                }
                asm volatile("cp.async.commit_group;" ::: "memory");
            }
            load_full(1, 64);

            for (int st = 0; st < SNK; ++st) {
                if (st == SNK-1) { asm volatile("cp.async.wait_group 0;" ::: "memory"); }
                else             { asm volatile("cp.async.wait_group 1;" ::: "memory"); }
                __syncthreads();
                if (st + 2 < SNK) load_full((st+2)%3, (st+2)*64);

                const uint32_t sb = base + (st%3)*SSTAGE;
                #pragma unroll
                for (int kk8 = 0; kk8 < 8; kk8 += 2) {
                    uint32_t ah[2][4], al[2][4];
                    #pragma unroll
                    for (int mt = 0; mt < 2; mt++) {
                        int row = wm*32 + mt*16 + lr;
                        uint32_t off = row*128 + ((((kk8 + lk) ^ (row & 7))) << 4);
                        LDSM4(ah[mt], sb + off);
                        LDSM4(al[mt], sb + 8192 + off);
                    }
                    uint32_t bh[2][2], bl[2][2];
                    {
                        int row = wn*16 + lr;
                        uint32_t off = row*128 + ((((kk8 + lk) ^ (row & 7))) << 4);
                        uint32_t r[4];
                        LDSM4(r, sb + 16384 + off);
                        bh[0][0]=r[0]; bh[1][0]=r[1]; bh[0][1]=r[2]; bh[1][1]=r[3];
                        LDSM4(r, sb + 24576 + off);
                        bl[0][0]=r[0]; bl[1][0]=r[1]; bl[0][1]=r[2]; bl[1][1]=r[3];
                    }
                    #pragma unroll
                    for (int mt = 0; mt < 2; mt++)
                        #pragma unroll
                        for (int nt = 0; nt < 2; nt++) {
                            mma_f16(acc[mt][nt], ah[mt], bh[nt]);
                            mma_f16(acc[mt][nt], ah[mt], bl[nt]);
                            mma_f16(acc[mt][nt], al[mt], bh[nt]);
                        }
                }
            }
            __syncthreads();

            if (role == 1) {
                float* pbuf = g_p1[(s-1) & 1];
                #pragma unroll
                for (int mt = 0; mt < 2; mt++)
                    #pragma unroll
                    for (int nt = 0; nt < 2; nt++) {
                        int r0  = am0 + wm*32 + mt*16 + (lane >> 2);
                        int col = n0 + wn*16 + nt*8 + (lane & 3)*2;
                        *reinterpret_cast<float2*>(&pbuf[(size_t)r0*G4 + col]) =
                            make_float2(acc[mt][nt][0], acc[mt][nt][1]);
                        *reinterpret_cast<float2*>(&pbuf[(size_t)(r0+8)*G4 + col]) =
                            make_float2(acc[mt][nt][2], acc[mt][nt][3]);
                    }
            } else {
                #pragma unroll
                for (int mt = 0; mt < 2; mt++)
                    #pragma unroll
                    for (int nt = 0; nt < 2; nt++) {
                        int r0 = wm*32 + mt*16 + (lane >> 2);
                        int c  = wn*16 + nt*8 + (lane & 3)*2;
                        *reinterpret_cast<float2*>(&gsh[r0*68 + c]) =
                            make_float2(acc[mt][nt][0], acc[mt][nt][1]);
                        *reinterpret_cast<float2*>(&gsh[(r0+8)*68 + c]) =
                            make_float2(acc[mt][nt][2], acc[mt][nt][3]);
                    }
                __syncthreads();

                const int hg = nb * 16;
                if (role == 0) {
                    __half* Ho = g_h0b[(s & 1) ^ 1][0];
                    __half* Lo = g_h0b[(s & 1) ^ 1][1];
                    for (int e = tid; e < 64*16; e += 256) {
                        int br = e >> 4, hl = e & 15;
                        int b = am0 + br;
                        float4 g = *reinterpret_cast<const float4*>(&gsh[br*68 + hl*4]);
                        int h = hg + hl;
                        size_t gb = ((size_t)(s*Bc + b))*G4 + h;
                        float gi = g.x + g_G0[gb];
                        float gf = g.y + g_G0[gb +   Hh];
                        float gg = g.z + g_G0[gb + 2*Hh];
                        float go = g.w + g_G0[gb + 3*Hh];
                        int ci = b*Hh + h;
                        float si = 1.f/(1.f+expf(-gi));
                        float sf = 1.f/(1.f+expf(-gf));
                        float so = 1.f/(1.f+expf(-go));
                        float cn = sf * g_c0[ci] + si * tanhf(gg);
                        float hn = so * tanhf(cn);
                        g_c0[ci] = cn;
                        __half hh, ll;
                        hf_split(hn, hh, ll);
                        Ho[ci] = hh; Lo[ci] = ll;
                    }
                } else {
                    const int u = s - 2;
                    const float* pbuf = g_p1[u & 1];
                    __half* Ho = g_h1b[(s & 1) ^ 1][0];
                    __half* Lo = g_h1b[(s & 1) ^ 1][1];
                    for (int e = tid; e < 64*16; e += 256) {
                        int br = e >> 4, hl = e & 15;
                        int b = am0 + br;
                        float4 g = *reinterpret_cast<const float4*>(&gsh[br*68 + hl*4]);
                        int h = hg + hl;
                        float4 p  = __ldcg(reinterpret_cast<const float4*>(&pbuf[(size_t)b*G4 + h*4]));
                        float4 bb = *reinterpret_cast<const float4*>(&g_bp1[h*4]);
                        float gi = g.x + p.x + bb.x;
                        float gf = g.y + p.y + bb.y;
                        float gg = g.z + p.z + bb.z;
                        float go = g.w + p.w + bb.w;
                        int ci = b*Hh + h;
                        float si = 1.f/(1.f+expf(-gi));
                        float sf = 1.f/(1.f+expf(-gf));
                        float so = 1.f/(1.f+expf(-go));
                        float cn = sf * g_c1[ci] + si * tanhf(gg);
                        float hn = so * tanhf(cn);
                        g_c1[ci] = cn;
                        __half hh, ll;
                        hf_split(hn, hh, ll);
                        Ho[ci] = hh; Lo[ci] = ll;
                        g_ysh[((size_t)u*Bc + b)*Hh + h] = hh;   // proj reads hi only
                    }
                }
            }
        }

        if (s + 1 < NSLOTS) {
            bool active_next = (role == 0) ? (s+1 < 64)
                             : (role == 1) ? (s+1 >= 1 && s+1 <= 64)
                             : (s+1 >= 2);
            if (active) __syncthreads();
            if (active_next) prefetch_B0();
            __syncthreads();
            if (tid == 0) {
                unsigned* bar = &g_bar;
                asm volatile("red.release.gpu.global.add.u32 [%0], 1;" :: "l"(bar) : "memory");
                unsigned target = (unsigned)GRID_STEP * (unsigned)(s + 1);
                unsigned v;
                do {
                    asm volatile("ld.acquire.gpu.global.u32 %0, [%1];" : "=r"(v) : "l"(bar) : "memory");
                    if (v >= target) break;
                    asm volatile("nanosleep.u32 64;");
                } while (true);
            }
            __syncthreads();
        }
    }
}

// ---------------- fp16 1-mma output projection (Ah x Bh only) ----------------
// Stage: Ah 16K | Bh 16K (k-chunk 64). 64KB smem -> 2 CTAs/SM retained.
#define PSTAGE   32768
#define PROJ_SMEM (2*PSTAGE)
#define PNK (Hh/64)        // 12 k-chunks

__global__ void __launch_bounds__(256) proj_mma(const float* __restrict__ b_out,
                                                float* __restrict__ out) {
    extern __shared__ char dsm[];
    const uint32_t base = smem_u32(dsm);
    const int tid  = threadIdx.x;
    const int t    = blockIdx.x;
    const int m0   = t * 128;
    const int n0   = blockIdx.y * 128;
    const int lane = tid & 31;
    const int warp = tid >> 5;
    const int wm   = warp >> 2;       // 0..1 (m 64 each)
    const int wn   = warp & 3;        // 0..3 (n 32 each)
    const int lr   = lane & 15;
    const int lk   = lane >> 4;

    float acc[4][4][4];
    #pragma unroll
    for (int i = 0; i < 4; i++)
        #pragma unroll
        for (int j = 0; j < 4; j++)
            #pragma unroll
            for (int r = 0; r < 4; r++) acc[i][j][r] = 0.f;

    auto load_stage = [&](int buf, int k0) {
        const uint32_t sb = base + buf*PSTAGE;
        #pragma unroll
        for (int i = 0; i < 8; i++) {
            int id  = tid + i*256;        // 0..2047
            int arr = id >> 10;           // 0: A, 1: B
            int w   = id & 1023;
            int row = w >> 3, ch = w & 7;
            uint32_t dst = sb + arr*16384 + row*128 + ((ch ^ (row & 7)) << 4);
            if (arr == 0) cp16(dst, &g_ysh[(size_t)(m0 + row)*Hh + k0 + ch*8]);
            else          cp16(dst, &g_Wh [(size_t)(n0 + row)*Hh + k0 + ch*8]);
        }
        asm volatile("cp.async.commit_group;" ::: "memory");
    };

    load_stage(0, 0);

    for (int s = 0; s < PNK; ++s) {
        asm volatile("cp.async.wait_group 0;" ::: "memory");
        __syncthreads();
        if (s + 1 < PNK) load_stage((s+1) & 1, (s+1)*64);

        const uint32_t sb = base + (s & 1)*PSTAGE;
        #pragma unroll
        for (int kk8 = 0; kk8 < 8; kk8 += 2) {
            uint32_t ah[4][4];
            #pragma unroll
            for (int mt = 0; mt < 4; mt++) {
                int row = wm*64 + mt*16 + lr;
                uint32_t off = row*128 + ((((kk8 + lk) ^ (row & 7))) << 4);
                LDSM4(ah[mt], sb + off);
            }
            uint32_t bh[4][2];
            #pragma unroll
            for (int np = 0; np < 2; np++) {
                int row = wn*32 + np*16 + lr;
                uint32_t off = row*128 + ((((kk8 + lk) ^ (row & 7))) << 4);
                uint32_t r[4];
                LDSM4(r, sb + 16384 + off);
                bh[np*2][0]=r[0]; bh[np*2+1][0]=r[1]; bh[np*2][1]=r[2]; bh[np*2+1][1]=r[3];
            }
            #pragma unroll
            for (int mt = 0; mt < 4; mt++)
                #pragma unroll
                for (int nt = 0; nt < 4; nt++)
                    mma_f16(acc[mt][nt], ah[mt], bh[nt]);
        }
    }

    #pragma unroll
    for (int nt = 0; nt < 4; nt++) {
        int col = n0 + wn*32 + nt*8 + (lane & 3)*2;
        float bb0 = b_out[col], bb1 = b_out[col + 1];
        #pragma unroll
        for (int mt = 0; mt < 4; mt++) {
            int r0 = wm*64 + mt*16 + (lane >> 2);
            float2* p0 = reinterpret_cast<float2*>(&out[((size_t)r0*Tc + t)*Vc + col]);
            *p0 = make_float2(acc[mt][nt][0] + bb0, acc[mt][nt][1] + bb1);
            float2* p1 = reinterpret_cast<float2*>(&out[((size_t)(r0+8)*Tc + t)*Vc + col]);
            *p1 = make_float2(acc[mt][nt][2] + bb0, acc[mt][nt][3] + bb1);
        }
    }
}

// ---------------- launch ----------------------------------------------------
extern "C" void kernel_launch(void* const* d_in, const int* in_sizes, int n_in,
                              void* d_out, int out_size) {
    const int*   src   = (const int*)  d_in[0];
    const int*   trg   = (const int*)  d_in[1];
    const float* bert  = (const float*)d_in[2];
    const float* emb   = (const float*)d_in[3];
    const float* W_ih  = (const float*)d_in[4];
    const float* W_hh  = (const float*)d_in[5];
    const float* b_ih  = (const float*)d_in[6];
    const float* b_hh  = (const float*)d_in[7];
    const float* W_out = (const float*)d_in[8];
    const float* b_out = (const float*)d_in[9];
    float* out = (float*)d_out;

    cudaFuncSetAttribute(proj_mma,     cudaFuncAttributeMaxDynamicSharedMemorySize, PROJ_SMEM);
    cudaFuncSetAttribute(step_persist, cudaFuncAttributeMaxDynamicSharedMemorySize, STEP_SMEM);
    cudaFuncSetAttribute(gemm_mma,     cudaFuncAttributeMaxDynamicSharedMemorySize, GMMA_SMEM);

    // 1. gather embeddings (fp16-split xs) + init h/c + reset grid barrier
    init_kernel<<<(Tc*Bc*Hh + 255)/256, 256>>>(src, trg, bert, emb);

    // 1b. W_out hi-only fp16
    __half* wh;
    cudaGetSymbolAddress((void**)&wh, g_Wh);
    split_wout<<<(Vc*Hh + 255)/256, 256>>>(W_out, wh, Vc*Hh);

    // 1c. split (+permute) all LSTM weights + biases (fp16 hi/lo)
    const float* Wih0 = W_ih;
    const float* Whh0 = W_hh;
    const float* Wih1 = W_ih + (size_t)G4 * Hh;
    const float* Whh1 = W_hh + (size_t)G4 * Hh;
    wsplit<<<(4*G4*Hh + 255)/256, 256>>>(Whh0, Wih1, Whh1, Wih0,
                                         b_ih, b_hh, b_ih + G4, b_hh + G4);

    // 2. hoisted layer-0 input GEMM on tensor cores (fp16 3-mma)
    gemm_mma<<<dim3(G4/128, (Tc*Bc)/128), 256, GMMA_SMEM>>>();

    // 3. persistent recurrence: 288 CTAs (2/SM), grid barrier per slot
    step_persist<<<GRID_STEP, 256, STEP_SMEM>>>();

    // 4. output projection on tensor cores (fp16 1-mma AhBh)
    proj_mma<<<dim3(Tc, Vc/128), 256, PROJ_SMEM>>>(b_out, out);
}

// round 17
// speedup vs baseline: 1.4249x; 1.0569x over previous
#include <cuda_runtime.h>
#include <cuda_fp16.h>
#include <math.h>
#include <stdint.h>

// Problem constants
#define Hh   768
#define Lc   2
#define Vc   32000
#define Bc   128
#define Tc   64
#define Sc   32
#define G4   (4*Hh)   // 3072

// ---------------- scratch (device globals; no allocations allowed) ----------
__device__ __align__(128) float g_G0[(size_t)Tc*Bc*G4]; // layer0 input gates (+biases), gate-major
__device__ __align__(128) float g_p1[2][Bc*G4];         // layer1 input-gate partials (permuted cols)
__device__ __align__(128) float g_bp1[G4];              // permuted (b_ih[1]+b_hh[1])
__device__ __align__(128) float g_b0[G4];               // b_ih[0]+b_hh[0] (gate-major)
__device__ unsigned g_bar;                              // grid barrier counter
// xs as fp16 hi/lo (written directly by init gather)
__device__ __align__(128) __half g_xsh[Tc*Bc*Hh];
__device__ __align__(128) __half g_xsl[Tc*Bc*Hh];
// h-state as fp16 hi/lo, ping-pong
__device__ __align__(128) __half g_h0b[2][2][Bc*Hh];
__device__ __align__(128) __half g_h1b[2][2][Bc*Hh];
// recurrence weights: [mat 0=Whh0,1=Wih1,2=Whh1][hi/lo], permuted rows p = h*4+gate
__device__ __align__(128) __half g_Wr[3][2][(size_t)G4*Hh];
// W_ih[0] split (gate-major rows, unpermuted)
__device__ __align__(128) __half g_Wi0[2][(size_t)G4*Hh];
// fp16 buffers for tensor-core projection (hi only; proj is 1-mma AhBh)
__device__ __align__(128) __half g_ysh[Tc*Bc*Hh];
__device__ __align__(128) __half g_Wh[(size_t)Vc*Hh];

// ---------------- mma.sync helpers ------------------------------------------
__device__ __forceinline__ uint32_t smem_u32(const void* p) {
    uint32_t a;
    asm("{ .reg .u64 t; cvta.to.shared.u64 t, %1; cvt.u32.u64 %0, t; }" : "=r"(a) : "l"(p));
    return a;
}
#define LDSM4(r, a) \
    asm volatile("ldmatrix.sync.aligned.m8n8.x4.shared.b16 {%0,%1,%2,%3}, [%4];" \
        : "=r"((r)[0]), "=r"((r)[1]), "=r"((r)[2]), "=r"((r)[3]) : "r"(a))

__device__ __forceinline__ void mma_f16(float* c, const uint32_t* a, const uint32_t* b) {
    asm volatile("mma.sync.aligned.m16n8k16.row.col.f32.f16.f16.f32 "
        "{%0,%1,%2,%3}, {%4,%5,%6,%7}, {%8,%9}, {%0,%1,%2,%3};"
        : "+f"(c[0]), "+f"(c[1]), "+f"(c[2]), "+f"(c[3])
        : "r"(a[0]), "r"(a[1]), "r"(a[2]), "r"(a[3]), "r"(b[0]), "r"(b[1]));
}
__device__ __forceinline__ void cp16(uint32_t dst, const void* src) {       // L2-only (cg)
    asm volatile("cp.async.cg.shared.global [%0], [%1], 16;" :: "r"(dst), "l"(src));
}
__device__ __forceinline__ void cp16ca(uint32_t dst, const void* src) {     // L1-cacheable
    asm volatile("cp.async.ca.shared.global [%0], [%1], 16;" :: "r"(dst), "l"(src));
}
__device__ __forceinline__ void hf_split(float v, __half& h, __half& l) {
    h = __float2half_rz(v);
    l = __float2half_rz(v - __half2float(h));
}

// ---------------- init: gather embeddings (split), init h ------------------
__global__ void init_kernel(const int* __restrict__ src, const int* __restrict__ trg,
                            const float* __restrict__ bert, const float* __restrict__ emb) {
    int idx = blockIdx.x * blockDim.x + threadIdx.x;
    if (idx == 0) g_bar = 0;                       // reset grid barrier each run
    if (idx < Tc*Bc*Hh) {
        int h = idx % Hh;
        int m = idx / Hh;          // m = t*Bc + b
        int b = m % Bc;
        int t = m / Bc;
        float v = emb[(size_t)trg[b*Tc + t] * Hh + h];
        __half hh, ll;
        hf_split(v, hh, ll);
        g_xsh[idx] = hh; g_xsl[idx] = ll;
    }
    if (idx < Bc*Hh) {
        int b = idx / Hh;
        float v = bert[(size_t)src[b*Sc] * Hh + (idx % Hh)];
        __half h, l;
        hf_split(v, h, l);
        g_h0b[0][0][idx] = h; g_h0b[0][1][idx] = l;
        g_h1b[0][0][idx] = h; g_h1b[0][1][idx] = l;
    }
}

// ---------------- fp16 hi-only split for W_out -------------------------------
__global__ void split_wout(const float* __restrict__ x, __half* __restrict__ hi, int n) {
    int i = blockIdx.x * 256 + threadIdx.x;
    if (i < n) hi[i] = __float2half_rz(x[i]);
}

// ---------------- weight split(+permute) -------------------------------------
__global__ void wsplit(const float* __restrict__ Whh0, const float* __restrict__ Wih1,
                       const float* __restrict__ Whh1, const float* __restrict__ Wih0,
                       const float* __restrict__ bih0, const float* __restrict__ bhh0,
                       const float* __restrict__ bih1, const float* __restrict__ bhh1) {
    int i = blockIdx.x * 256 + threadIdx.x;
    const int per = G4 * Hh;
    if (i < 4*per) {
        int mat = i / per;
        int rem = i % per;
        int r = rem / Hh, k = rem % Hh;
        __half h, l;
        if (mat < 3) {
            const float* srcp = (mat == 0) ? Whh0 : (mat == 1 ? Wih1 : Whh1);
            hf_split(srcp[(size_t)r*Hh + k], h, l);
            int p = (r % Hh)*4 + (r / Hh);
            g_Wr[mat][0][(size_t)p*Hh + k] = h;
            g_Wr[mat][1][(size_t)p*Hh + k] = l;
        } else {
            hf_split(Wih0[(size_t)r*Hh + k], h, l);
            g_Wi0[0][(size_t)r*Hh + k] = h;
            g_Wi0[1][(size_t)r*Hh + k] = l;
        }
    }
    if (i < G4) {
        int p = (i % Hh)*4 + (i / Hh);
        g_bp1[p] = bih1[i] + bhh1[i];
        g_b0[i]  = bih0[i] + bhh0[i];
    }
}

// ---------------- mma hoisted layer0 input GEMM (fp16 3-mma, R10-exact) ------
#define GSTAGE   32768
#define GMMA_SMEM (3*GSTAGE)

__global__ void __launch_bounds__(256) gemm_mma() {
    extern __shared__ char dsm[];
    const uint32_t base = smem_u32(dsm);
    const int tid  = threadIdx.x;
    const int m0   = blockIdx.y * 128;
    const int n0   = blockIdx.x * 128;
    const int lane = tid & 31;
    const int warp = tid >> 5;
    const int wm   = warp >> 2;
    const int wn   = warp & 3;
    const int lr   = lane & 15;
    const int lk   = lane >> 4;
    const int NS   = Hh/32;

    float acc[4][4][4];
    #pragma unroll
    for (int i = 0; i < 4; i++)
        #pragma unroll
        for (int j = 0; j < 4; j++)
            #pragma unroll
            for (int r = 0; r < 4; r++) acc[i][j][r] = 0.f;

    auto load_stage = [&](int buf, int k0) {
        const uint32_t sb = base + buf*GSTAGE;
        #pragma unroll
        for (int i = 0; i < 8; i++) {
            int id  = tid + i*256;
            int arr = id >> 9;
            int w   = id & 511;
            int row = w >> 2, ch = w & 3;
            uint32_t dst = sb + arr*8192 + row*64 + ((ch ^ (row & 3)) << 4);
            const __half* src;
            if      (arr == 0) src = &g_xsh[(size_t)(m0 + row)*Hh + k0 + ch*8];
            else if (arr == 1) src = &g_xsl[(size_t)(m0 + row)*Hh + k0 + ch*8];
            else if (arr == 2) src = &g_Wi0[0][(size_t)(n0 + row)*Hh + k0 + ch*8];
            else               src = &g_Wi0[1][(size_t)(n0 + row)*Hh + k0 + ch*8];
            cp16(dst, src);
        }
        asm volatile("cp.async.commit_group;" ::: "memory");
    };

    load_stage(0, 0);
    load_stage(1, 32);

    for (int s = 0; s < NS; ++s) {
        if (s + 1 < NS) { asm volatile("cp.async.wait_group 1;" ::: "memory"); }
        else            { asm volatile("cp.async.wait_group 0;" ::: "memory"); }
        __syncthreads();
        if (s + 2 < NS) load_stage((s+2)%3, (s+2)*32);

        const uint32_t sb = base + (s%3)*GSTAGE;
        #pragma unroll
        for (int kk8 = 0; kk8 < 4; kk8 += 2) {
            uint32_t ah[4][4], al[4][4];
            #pragma unroll
            for (int mt = 0; mt < 4; mt++) {
                int row = wm*64 + mt*16 + lr;
                uint32_t off = row*64 + ((((kk8 + lk) ^ (row & 3))) << 4);
                LDSM4(ah[mt], sb + off);
                LDSM4(al[mt], sb + 8192 + off);
            }
            uint32_t bh[4][2], bl[4][2];
            #pragma unroll
            for (int np = 0; np < 2; np++) {
                int row = wn*32 + np*16 + lr;
                uint32_t off = row*64 + ((((kk8 + lk) ^ (row & 3))) << 4);
                uint32_t r[4];
                LDSM4(r, sb + 16384 + off);
                bh[np*2][0]=r[0]; bh[np*2+1][0]=r[1]; bh[np*2][1]=r[2]; bh[np*2+1][1]=r[3];
                LDSM4(r, sb + 24576 + off);
                bl[np*2][0]=r[0]; bl[np*2+1][0]=r[1]; bl[np*2][1]=r[2]; bl[np*2+1][1]=r[3];
            }
            #pragma unroll
            for (int mt = 0; mt < 4; mt++)
                #pragma unroll
                for (int nt = 0; nt < 4; nt++) {
                    mma_f16(acc[mt][nt], ah[mt], bh[nt]);
                    mma_f16(acc[mt][nt], ah[mt], bl[nt]);
                    mma_f16(acc[mt][nt], al[mt], bh[nt]);
                }
        }
    }

    #pragma unroll
    for (int nt = 0; nt < 4; nt++) {
        int col = n0 + wn*32 + nt*8 + (lane & 3)*2;
        float bb0 = g_b0[col], bb1 = g_b0[col + 1];
        #pragma unroll
        for (int mt = 0; mt < 4; mt++) {
            int r0 = m0 + wm*64 + mt*16 + (lane >> 2);
            *reinterpret_cast<float2*>(&g_G0[(size_t)r0*G4 + col]) =
                make_float2(acc[mt][nt][0] + bb0, acc[mt][nt][1] + bb1);
            *reinterpret_cast<float2*>(&g_G0[(size_t)(r0+8)*G4 + col]) =
                make_float2(acc[mt][nt][2] + bb0, acc[mt][nt][3] + bb1);
        }
    }
}

// ---------------- persistent mma recurrence (288 CTAs, reg-resident c-state) -
// R16 structure + : c-state held in registers across slots (CTA-private slice),
// G0/p1 register-prefetched under the k-loop, one redundant sync removed.
#define SSTAGE 32768   // Ah 8K | Al 8K | Bh 8K | Bl 8K
#define STEP_SMEM (3*SSTAGE)
#define NSLOTS 66
#define GRID_STEP 288
#define SNK (Hh/64)    // 12 k-chunks

__global__ void __launch_bounds__(256, 2) step_persist() {
    extern __shared__ char dsm[];
    const uint32_t base = smem_u32(dsm);
    const int tid  = threadIdx.x;
    const int bx   = blockIdx.x;
    const int lane = tid & 31;
    const int warp = tid >> 5;
    const int wm   = warp >> 2;        // 0..1 (m 32 each)
    const int wn   = warp & 3;         // 0..3 (n 16 each)
    const int lr   = lane & 15;
    const int lk   = lane >> 4;

    int role, nb, mh;
    const __half *Bh, *Bl;
    if (bx < 96)       { role = 0; nb = bx >> 1;         Bh = g_Wr[0][0]; Bl = g_Wr[0][1]; }
    else if (bx < 192) { role = 1; nb = (bx - 96) >> 1;  Bh = g_Wr[1][0]; Bl = g_Wr[1][1]; }
    else               { role = 2; nb = (bx - 192) >> 1; Bh = g_Wr[2][0]; Bl = g_Wr[2][1]; }
    mh = bx & 1;
    const int n0  = nb * 64;
    const int am0 = mh * 64;           // batch-half row offset
    const int hg  = nb * 16;
    float* gsh = reinterpret_cast<float*>(dsm + SSTAGE);   // [64][68]

    // c-state: this CTA's 64x16 slice is touched by no other CTA -> registers.
    float creg[4] = {0.f, 0.f, 0.f, 0.f};

    auto prefetch_B0 = [&]() {
        #pragma unroll
        for (int q = 0; q < 2; ++q) {
            int id  = tid + q*256;
            int row = id >> 3, ch = id & 7;
            uint32_t off = row*128 + ((ch ^ (row & 7)) << 4);
            cp16ca(base + 16384 + off, &Bh[(size_t)(n0 + row)*Hh + ch*8]);
            cp16ca(base + 24576 + off, &Bl[(size_t)(n0 + row)*Hh + ch*8]);
        }
    };

    if (role == 0) prefetch_B0();

    for (int s = 0; s < NSLOTS; ++s) {
        bool active = (role == 0) ? (s < 64) : (role == 1) ? (s >= 1 && s <= 64) : (s >= 2);
        if (active) {
            const __half* Ah = (role == 2) ? g_h1b[s & 1][0] : g_h0b[s & 1][0];
            const __half* Al = (role == 2) ? g_h1b[s & 1][1] : g_h0b[s & 1][1];

            float acc[2][2][4];
            #pragma unroll
            for (int i = 0; i < 2; i++)
                #pragma unroll
                for (int j = 0; j < 2; j++)
                    #pragma unroll
                    for (int r = 0; r < 4; r++) acc[i][j][r] = 0.f;

            auto load_full = [&](int buf, int k0) {
                const uint32_t sb = base + buf*SSTAGE;
                #pragma unroll
                for (int q = 0; q < 2; ++q) {
                    int id  = tid + q*256;
                    int row = id >> 3, ch = id & 7;
                    uint32_t off = row*128 + ((ch ^ (row & 7)) << 4);
                    cp16(sb + off,           &Ah[(size_t)(am0 + row)*Hh + k0 + ch*8]);
                    cp16(sb + 8192  + off,   &Al[(size_t)(am0 + row)*Hh + k0 + ch*8]);
                    cp16ca(sb + 16384 + off, &Bh[(size_t)(n0 + row)*Hh + k0 + ch*8]);
                    cp16ca(sb + 24576 + off, &Bl[(size_t)(n0 + row)*Hh + k0 + ch*8]);
                }
                asm volatile("cp.async.commit_group;" ::: "memory");
            };

            {
                #pragma unroll
                for (int q = 0; q < 2; ++q) {
                    int id  = tid + q*256;
                    int row = id >> 3, ch = id & 7;
                    uint32_t off = row*128 + ((ch ^ (row & 7)) << 4);
                    cp16(base + off,          &Ah[(size_t)(am0 + row)*Hh + ch*8]);
                    cp16(base + 8192  + off,  &Al[(size_t)(am0 + row)*Hh + ch*8]);
                }
                asm volatile("cp.async.commit_group;" ::: "memory");
            }
            load_full(1, 64);

            // register-prefetch epilogue operands (latency hidden by k-loop)
            float pre[4][4];
            if (role == 0) {
                #pragma unroll
                for (int i = 0; i < 4; i++) {
                    int e = tid + i*256;
                    int br = e >> 4, hl = e & 15;
                    size_t gb = ((size_t)(s*Bc + am0 + br))*G4 + hg + hl;
                    pre[i][0] = __ldcg(&g_G0[gb]);
                    pre[i][1] = __ldcg(&g_G0[gb +   Hh]);
                    pre[i][2] = __ldcg(&g_G0[gb + 2*Hh]);
                    pre[i][3] = __ldcg(&g_G0[gb + 3*Hh]);
                }
            } else if (role == 2) {
                const float* pbuf = g_p1[(s-2) & 1];
                #pragma unroll
                for (int i = 0; i < 4; i++) {
                    int e = tid + i*256;
                    int br = e >> 4, hl = e & 15;
                    float4 p = __ldcg(reinterpret_cast<const float4*>(
                        &pbuf[(size_t)(am0 + br)*G4 + (hg + hl)*4]));
                    pre[i][0] = p.x; pre[i][1] = p.y; pre[i][2] = p.z; pre[i][3] = p.w;
                }
            }

            for (int st = 0; st < SNK; ++st) {
                if (st == SNK-1) { asm volatile("cp.async.wait_group 0;" ::: "memory"); }
                else             { asm volatile("cp.async.wait_group 1;" ::: "memory"); }
                __syncthreads();
                if (st + 2 < SNK) load_full((st+2)%3, (st+2)*64);

                const uint32_t sb = base + (st%3)*SSTAGE;
                #pragma unroll
                for (int kk8 = 0; kk8 < 8; kk8 += 2) {
                    uint32_t ah[2][4], al[2][4];
                    #pragma unroll
                    for (int mt = 0; mt < 2; mt++) {
                        int row = wm*32 + mt*16 + lr;
                        uint32_t off = row*128 + ((((kk8 + lk) ^ (row & 7))) << 4);
                        LDSM4(ah[mt], sb + off);
                        LDSM4(al[mt], sb + 8192 + off);
                    }
                    uint32_t bh[2][2], bl[2][2];
                    {
                        int row = wn*16 + lr;
                        uint32_t off = row*128 + ((((kk8 + lk) ^ (row & 7))) << 4);
                        uint32_t r[4];
                        LDSM4(r, sb + 16384 + off);
                        bh[0][0]=r[0]; bh[1][0]=r[1]; bh[0][1]=r[2]; bh[1][1]=r[3];
                        LDSM4(r, sb + 24576 + off);
                        bl[0][0]=r[0]; bl[1][0]=r[1]; bl[0][1]=r[2]; bl[1][1]=r[3];
                    }
                    #pragma unroll
                    for (int mt = 0; mt < 2; mt++)
                        #pragma unroll
                        for (int nt = 0; nt < 2; nt++) {
                            mma_f16(acc[mt][nt], ah[mt], bh[nt]);
                            mma_f16(acc[mt][nt], ah[mt], bl[nt]);
                            mma_f16(acc[mt][nt], al[mt], bh[nt]);
                        }
                }
            }
            __syncthreads();     // all warps past the k-loop

            if (role == 1) {
                float* pbuf = g_p1[(s-1) & 1];
                #pragma unroll
                for (int mt = 0; mt < 2; mt++)
                    #pragma unroll
                    for (int nt = 0; nt < 2; nt++) {
                        int r0  = am0 + wm*32 + mt*16 + (lane >> 2);
                        int col = n0 + wn*16 + nt*8 + (lane & 3)*2;
                        *reinterpret_cast<float2*>(&pbuf[(size_t)r0*G4 + col]) =
                            make_float2(acc[mt][nt][0], acc[mt][nt][1]);
                        *reinterpret_cast<float2*>(&pbuf[(size_t)(r0+8)*G4 + col]) =
                            make_float2(acc[mt][nt][2], acc[mt][nt][3]);
                    }
            } else {
                #pragma unroll
                for (int mt = 0; mt < 2; mt++)
                    #pragma unroll
                    for (int nt = 0; nt < 2; nt++) {
                        int r0 = wm*32 + mt*16 + (lane >> 2);
                        int c  = wn*16 + nt*8 + (lane & 3)*2;
                        *reinterpret_cast<float2*>(&gsh[r0*68 + c]) =
                            make_float2(acc[mt][nt][0], acc[mt][nt][1]);
                        *reinterpret_cast<float2*>(&gsh[(r0+8)*68 + c]) =
                            make_float2(acc[mt][nt][2], acc[mt][nt][3]);
                    }
                __syncthreads();

                if (role == 0) {
                    __half* Ho = g_h0b[(s & 1) ^ 1][0];
                    __half* Lo = g_h0b[(s & 1) ^ 1][1];
                    #pragma unroll
                    for (int i = 0; i < 4; i++) {
                        int e = tid + i*256;
                        int br = e >> 4, hl = e & 15;
                        int b = am0 + br;
                        float4 g = *reinterpret_cast<const float4*>(&gsh[br*68 + hl*4]);
                        int h = hg + hl;
                        float gi = g.x + pre[i][0];
                        float gf = g.y + pre[i][1];
                        float gg = g.z + pre[i][2];
                        float go = g.w + pre[i][3];
                        int ci = b*Hh + h;
                        float si = 1.f/(1.f+expf(-gi));
                        float sf = 1.f/(1.f+expf(-gf));
                        float so = 1.f/(1.f+expf(-go));
                        float cn = sf * creg[i] + si * tanhf(gg);
                        float hn = so * tanhf(cn);
                        creg[i] = cn;
                        __half hh, ll;
                        hf_split(hn, hh, ll);
                        Ho[ci] = hh; Lo[ci] = ll;
                    }
                } else {
                    const int u = s - 2;
                    __half* Ho = g_h1b[(s & 1) ^ 1][0];
                    __half* Lo = g_h1b[(s & 1) ^ 1][1];
                    #pragma unroll
                    for (int i = 0; i < 4; i++) {
                        int e = tid + i*256;
                        int br = e >> 4, hl = e & 15;
                        int b = am0 + br;
                        float4 g = *reinterpret_cast<const float4*>(&gsh[br*68 + hl*4]);
                        int h = hg + hl;
                        float4 bb = *reinterpret_cast<const float4*>(&g_bp1[h*4]);
                        float gi = g.x + pre[i][0] + bb.x;
                        float gf = g.y + pre[i][1] + bb.y;
                        float gg = g.z + pre[i][2] + bb.z;
                        float go = g.w + pre[i][3] + bb.w;
                        int ci = b*Hh + h;
                        float si = 1.f/(1.f+expf(-gi));
                        float sf = 1.f/(1.f+expf(-gf));
                        float so = 1.f/(1.f+expf(-go));
                        float cn = sf * creg[i] + si * tanhf(gg);
                        float hn = so * tanhf(cn);
                        creg[i] = cn;
                        __half hh, ll;
                        hf_split(hn, hh, ll);
                        Ho[ci] = hh; Lo[ci] = ll;
                        g_ysh[((size_t)u*Bc + b)*Hh + h] = hh;   // proj reads hi only
                    }
                }
            }
        }

        if (s + 1 < NSLOTS) {
            bool active_next = (role == 0) ? (s+1 < 64)
                             : (role == 1) ? (s+1 >= 1 && s+1 <= 64)
                             : (s+1 >= 2);
            if (active_next) prefetch_B0();   // stage0 B region: last read >=2 syncs ago
            __syncthreads();                  // orders all CTA work before the release
            if (tid == 0) {
                unsigned* bar = &g_bar;
                asm volatile("red.release.gpu.global.add.u32 [%0], 1;" :: "l"(bar) : "memory");
                unsigned target = (unsigned)GRID_STEP * (unsigned)(s + 1);
                unsigned v;
                do {
                    asm volatile("ld.acquire.gpu.global.u32 %0, [%1];" : "=r"(v) : "l"(bar) : "memory");
                    if (v >= target) break;
                    asm volatile("nanosleep.u32 64;");
                } while (true);
            }
            __syncthreads();
        }
    }
}

// ---------------- fp16 1-mma output projection (R16-exact) -------------------
#define PSTAGE   32768
#define PROJ_SMEM (2*PSTAGE)
#define PNK (Hh/64)        // 12 k-chunks

__global__ void __launch_bounds__(256) proj_mma(const float* __restrict__ b_out,
                                                float* __restrict__ out) {
    extern __shared__ char dsm[];
    const uint32_t base = smem_u32(dsm);
    const int tid  = threadIdx.x;
    const int t    = blockIdx.x;
    const int m0   = t * 128;
    const int n0   = blockIdx.y * 128;
    const int lane = tid & 31;
    const int warp = tid >> 5;
    const int wm   = warp >> 2;       // 0..1 (m 64 each)
    const int wn   = warp & 3;        // 0..3 (n 32 each)
    const int lr   = lane & 15;
    const int lk   = lane >> 4;

    float acc[4][4][4];
    #pragma unroll
    for (int i = 0; i < 4; i++)
        #pragma unroll
        for (int j = 0; j < 4; j++)
            #pragma unroll
            for (int r = 0; r < 4; r++) acc[i][j][r] = 0.f;

    auto load_stage = [&](int buf, int k0) {
        const uint32_t sb = base + buf*PSTAGE;
        #pragma unroll
        for (int i = 0; i < 8; i++) {
            int id  = tid + i*256;        // 0..2047
            int arr = id >> 10;           // 0: A, 1: B
            int w   = id & 1023;
            int row = w >> 3, ch = w & 7;
            uint32_t dst = sb + arr*16384 + row*128 + ((ch ^ (row & 7)) << 4);
            if (arr == 0) cp16(dst, &g_ysh[(size_t)(m0 + row)*Hh + k0 + ch*8]);
            else          cp16(dst, &g_Wh [(size_t)(n0 + row)*Hh + k0 + ch*8]);
        }
        asm volatile("cp.async.commit_group;" ::: "memory");
    };

    load_stage(0, 0);

    for (int s = 0; s < PNK; ++s) {
        asm volatile("cp.async.wait_group 0;" ::: "memory");
        __syncthreads();
        if (s + 1 < PNK) load_stage((s+1) & 1, (s+1)*64);

        const uint32_t sb = base + (s & 1)*PSTAGE;
        #pragma unroll
        for (int kk8 = 0; kk8 < 8; kk8 += 2) {
            uint32_t ah[4][4];
            #pragma unroll
            for (int mt = 0; mt < 4; mt++) {
                int row = wm*64 + mt*16 + lr;
                uint32_t off = row*128 + ((((kk8 + lk) ^ (row & 7))) << 4);
                LDSM4(ah[mt], sb + off);
            }
            uint32_t bh[4][2];
            #pragma unroll
            for (int np = 0; np < 2; np++) {
                int row = wn*32 + np*16 + lr;
                uint32_t off = row*128 + ((((kk8 + lk) ^ (row & 7))) << 4);
                uint32_t r[4];
                LDSM4(r, sb + 16384 + off);
                bh[np*2][0]=r[0]; bh[np*2+1][0]=r[1]; bh[np*2][1]=r[2]; bh[np*2+1][1]=r[3];
            }
            #pragma unroll
            for (int mt = 0; mt < 4; mt++)
                #pragma unroll
                for (int nt = 0; nt < 4; nt++)
                    mma_f16(acc[mt][nt], ah[mt], bh[nt]);
        }
    }

    #pragma unroll
    for (int nt = 0; nt < 4; nt++) {
        int col = n0 + wn*32 + nt*8 + (lane & 3)*2;
        float bb0 = b_out[col], bb1 = b_out[col + 1];
        #pragma unroll
        for (int mt = 0; mt < 4; mt++) {
            int r0 = wm*64 + mt*16 + (lane >> 2);
            float2* p0 = reinterpret_cast<float2*>(&out[((size_t)r0*Tc + t)*Vc + col]);
            *p0 = make_float2(acc[mt][nt][0] + bb0, acc[mt][nt][1] + bb1);
            float2* p1 = reinterpret_cast<float2*>(&out[((size_t)(r0+8)*Tc + t)*Vc + col]);
            *p1 = make_float2(acc[mt][nt][2] + bb0, acc[mt][nt][3] + bb1);
        }
    }
}

// ---------------- launch ----------------------------------------------------
extern "C" void kernel_launch(void* const* d_in, const int* in_sizes, int n_in,
                              void* d_out, int out_size) {
    const int*   src   = (const int*)  d_in[0];
    const int*   trg   = (const int*)  d_in[1];
    const float* bert  = (const float*)d_in[2];
    const float* emb   = (const float*)d_in[3];
    const float* W_ih  = (const float*)d_in[4];
    const float* W_hh  = (const float*)d_in[5];
    const float* b_ih  = (const float*)d_in[6];
    const float* b_hh  = (const float*)d_in[7];
    const float* W_out = (const float*)d_in[8];
    const float* b_out = (const float*)d_in[9];
    float* out = (float*)d_out;

    cudaFuncSetAttribute(proj_mma,     cudaFuncAttributeMaxDynamicSharedMemorySize, PROJ_SMEM);
    cudaFuncSetAttribute(step_persist, cudaFuncAttributeMaxDynamicSharedMemorySize, STEP_SMEM);
    cudaFuncSetAttribute(gemm_mma,     cudaFuncAttributeMaxDynamicSharedMemorySize, GMMA_SMEM);

    // 1. gather embeddings (fp16-split xs) + init h + reset grid barrier
    init_kernel<<<(Tc*Bc*Hh + 255)/256, 256>>>(src, trg, bert, emb);

    // 1b. W_out hi-only fp16
    __half* wh;
    cudaGetSymbolAddress((void**)&wh, g_Wh);
    split_wout<<<(Vc*Hh + 255)/256, 256>>>(W_out, wh, Vc*Hh);

    // 1c. split (+permute) all LSTM weights + biases (fp16 hi/lo)
    const float* Wih0 = W_ih;
    const float* Whh0 = W_hh;
    const float* Wih1 = W_ih + (size_t)G4 * Hh;
    const float* Whh1 = W_hh + (size_t)G4 * Hh;
    wsplit<<<(4*G4*Hh + 255)/256, 256>>>(Whh0, Wih1, Whh1, Wih0,
                                         b_ih, b_hh, b_ih + G4, b_hh + G4);

    // 2. hoisted layer-0 input GEMM on tensor cores (fp16 3-mma)
    gemm_mma<<<dim3(G4/128, (Tc*Bc)/128), 256, GMMA_SMEM>>>();

    // 3. persistent recurrence: 288 CTAs (2/SM), reg-resident c-state
    step_persist<<<GRID_STEP, 256, STEP_SMEM>>>();

    // 4. output projection on tensor cores (fp16 1-mma AhBh)
    proj_mma<<<dim3(Tc, Vc/128), 256, PROJ_SMEM>>>(b_out, out);
}